// round 9
// baseline (speedup 1.0000x reference)
#include <cuda_runtime.h>
#include <math.h>

#define Bn 32
#define Nn 1024
#define Fn 128
#define Dn 128

// dk = (D^-0.5)/N = 1/(sqrt(128)*1024)
#define DKC 8.6316745750311e-05f

// ---------------- scratch (device globals) ----------------
__device__ float g_M[Fn * Fn];
__device__ float g_Apart[Bn][4][Fn];
__device__ float g_wcomb[Bn][Fn];
__device__ float g_ccomb[Bn];
__device__ float g_n2part[Bn][4];
__device__ float g_invn[Bn];
__device__ float g_Zpart[Bn][4];
__device__ float g_upart[Bn][4][Fn];
__device__ float g_invZ[Bn];
__device__ int   g_cnt1[Bn], g_cnt2[Bn], g_cnt3[Bn], g_cnt4[Bn];
__device__ int   g_flagW[Bn], g_flagN[Bn], g_flagZ[Bn];
__device__ int   g_cntM, g_flagM, g_cntR;

// ---------------- helpers ----------------
__device__ __forceinline__ unsigned f2tf(float f) {
    unsigned r; asm("cvt.rna.tf32.f32 %0, %1;" : "=r"(r) : "f"(f)); return r;
}
__device__ __forceinline__ void mma_tf32(float c[4], unsigned a0, unsigned a1,
                                         unsigned a2, unsigned a3,
                                         unsigned b0, unsigned b1) {
    asm("mma.sync.aligned.m16n8k8.row.col.f32.tf32.tf32.f32 "
        "{%0,%1,%2,%3}, {%4,%5,%6,%7}, {%8,%9}, {%0,%1,%2,%3};"
        : "+f"(c[0]), "+f"(c[1]), "+f"(c[2]), "+f"(c[3])
        : "r"(a0), "r"(a1), "r"(a2), "r"(a3), "r"(b0), "r"(b1));
}
__device__ __forceinline__ void waitflag(int* f, int t) {
    if (t == 0) { while (atomicAdd(f, 0) == 0) __nanosleep(64); }
    __syncthreads();
    __threadfence();
}

// ============ k1: persistent fused kernel, 128 blocks x 512 threads ============
#define STM 129      // M (tf32) row stride
#define STX 66       // fp32 X[f][atom] stride
#define STXF 72      // tf32 X[g][atom] stride (conflict-free B-frag loads)
#define STY 66       // Y[f][atom] stride
#define K1_SMEM ((Fn * STM + Fn * STX + Fn * STXF + Fn * STY) * 4)

__global__ void __launch_bounds__(512, 1) k1(const float* __restrict__ aq,
                                             const float* __restrict__ mask,
                                             const float* __restrict__ Wq,
                                             const float* __restrict__ Wk,
                                             const float* __restrict__ bq,
                                             const float* __restrict__ bk,
                                             const float* __restrict__ Wv,
                                             const float* __restrict__ bv,
                                             float* __restrict__ attn_out,
                                             float* __restrict__ ctx_out) {
    extern __shared__ float sm[];
    unsigned* sMu   = (unsigned*)sm;                 // [128][129] tf32 M
    float*    sXT   = sm + Fn * STM;                 // [128 f][66] fp32 tile
    unsigned* sXtfu = (unsigned*)(sXT + Fn * STX);   // [128 g][72] tf32 tile
    float*    sY    = sXT + Fn * STX + Fn * STXF;    // [128 f][66] Y = M X
    __shared__ float sWq[128], sA[128], sT[128], sbq[128], sWc[128];
    __shared__ float sMaskAll[256], aggAll[256];
    __shared__ float sStage[2048], sTmp[512], sred[16];
    __shared__ int isL1, isL3;

    const int p = blockIdx.x;            // 0..127
    const int b = p >> 2, j = p & 3;     // batch, quarter
    const int t = threadIdx.x;
    const int warp = t >> 5, lane = t & 31;
    const int gid = lane >> 2, tid4 = lane & 3;
    const int atomBase = j * 256;

    // ---------- A0: compute M row p (4-way k-split across 512 threads) ----------
    if (t < 128) sWq[t] = Wq[p * Fn + t];
    __syncthreads();
    {
        int c = t & 127, kq = t >> 7;            // kq 0..3
        const float4* wk4 = reinterpret_cast<const float4*>(Wk + c * Fn + kq * 32);
        const float* sq = sWq + kq * 32;
        float a0 = 0.f, a1 = 0.f;
        #pragma unroll
        for (int q = 0; q < 8; q += 2) {
            float4 v0 = wk4[q], v1 = wk4[q + 1];
            a0 = fmaf(sq[4*q + 0], v0.x, a0); a0 = fmaf(sq[4*q + 1], v0.y, a0);
            a0 = fmaf(sq[4*q + 2], v0.z, a0); a0 = fmaf(sq[4*q + 3], v0.w, a0);
            a1 = fmaf(sq[4*q + 4], v1.x, a1); a1 = fmaf(sq[4*q + 5], v1.y, a1);
            a1 = fmaf(sq[4*q + 6], v1.z, a1); a1 = fmaf(sq[4*q + 7], v1.w, a1);
        }
        sTmp[t] = a0 + a1;
    }
    __syncthreads();
    if (t < 128) g_M[p * Fn + t] = (sTmp[t] + sTmp[t + 128]) + (sTmp[t + 256] + sTmp[t + 384]);
    __threadfence();
    __syncthreads();
    if (t == 0 && atomicAdd(&g_cntM, 1) == 127) atomicExch(&g_flagM, 1);

    // ---------- A1: colsum of my 256 atoms (cold gmem, coalesced float4) ----------
    {
        int fq = (t & 31) * 4, rg = t >> 5;      // 16 groups x 16 rows
        const float* pp = aq + ((size_t)(b * Nn + atomBase + rg * 16)) * Fn + fq;
        float4 s0 = {0,0,0,0}, s1 = {0,0,0,0}, s2 = {0,0,0,0}, s3 = {0,0,0,0};
        #pragma unroll
        for (int r = 0; r < 16; r += 4) {
            float4 v0 = *reinterpret_cast<const float4*>(pp + (r + 0) * Fn);
            float4 v1 = *reinterpret_cast<const float4*>(pp + (r + 1) * Fn);
            float4 v2 = *reinterpret_cast<const float4*>(pp + (r + 2) * Fn);
            float4 v3 = *reinterpret_cast<const float4*>(pp + (r + 3) * Fn);
            s0.x += v0.x; s0.y += v0.y; s0.z += v0.z; s0.w += v0.w;
            s1.x += v1.x; s1.y += v1.y; s1.z += v1.z; s1.w += v1.w;
            s2.x += v2.x; s2.y += v2.y; s2.z += v2.z; s2.w += v2.w;
            s3.x += v3.x; s3.y += v3.y; s3.z += v3.z; s3.w += v3.w;
        }
        sStage[rg * 128 + fq + 0] = (s0.x + s1.x) + (s2.x + s3.x);
        sStage[rg * 128 + fq + 1] = (s0.y + s1.y) + (s2.y + s3.y);
        sStage[rg * 128 + fq + 2] = (s0.z + s1.z) + (s2.z + s3.z);
        sStage[rg * 128 + fq + 3] = (s0.w + s1.w) + (s2.w + s3.w);
    }
    if (t < 256) sMaskAll[t] = mask[b * Nn + atomBase + t];
    __syncthreads();
    if (t < 128) {
        float s = 0.f;
        #pragma unroll
        for (int g = 0; g < 16; g++) s += sStage[g * 128 + t];
        g_Apart[b][j][t] = s;
    }
    __threadfence();
    __syncthreads();
    if (t == 0) isL1 = (atomicAdd(&g_cnt1[b], 1) == 3);
    __syncthreads();

    // ---------- A2: last block of batch computes wcomb/ccomb (k-split) ----------
    if (isL1) {
        if (t < 128) {
            float s = 0.f;
            #pragma unroll
            for (int c = 0; c < 4; c++) s += __ldcg(&g_Apart[b][c][t]);
            sA[t] = s;
            sbq[t] = bq[t];
        }
        __syncthreads();
        {   // S: sT[c] = sum_f Wk[f,c]*A[f] + 1023*bk[c]   (4-way f-split)
            int c = t & 127, kq = t >> 7;
            float s0 = 0.f, s1 = 0.f;
            int f0 = kq * 32;
            #pragma unroll 8
            for (int f = f0; f < f0 + 32; f += 2) {
                s0 = fmaf(Wk[(f + 0) * Fn + c], sA[f + 0], s0);
                s1 = fmaf(Wk[(f + 1) * Fn + c], sA[f + 1], s1);
            }
            sTmp[t] = s0 + s1;
        }
        __syncthreads();
        if (t < 128) sT[t] = (sTmp[t] + sTmp[t + 128]) + (sTmp[t + 256] + sTmp[t + 384]) + 1023.0f * bk[t];
        __syncthreads();
        {   // wcomb[c] = sum_d Wq[c,d]*sT[d] - Wk[c,d]*sbq[d]  (4-way d-split)
            int c = t & 127, kq = t >> 7;
            const float4* wq4 = reinterpret_cast<const float4*>(Wq + c * Fn + kq * 32);
            const float4* wk4 = reinterpret_cast<const float4*>(Wk + c * Fn + kq * 32);
            const float* tp = sT + kq * 32;
            const float* bp = sbq + kq * 32;
            float w0 = 0.f, w1 = 0.f;
            #pragma unroll
            for (int q = 0; q < 8; q++) {
                float4 a = wq4[q], b4 = wk4[q];
                int d0 = 4 * q;
                w0 = fmaf(a.x, tp[d0 + 0], w0);  w1 = fmaf(-b4.x, bp[d0 + 0], w1);
                w0 = fmaf(a.y, tp[d0 + 1], w0);  w1 = fmaf(-b4.y, bp[d0 + 1], w1);
                w0 = fmaf(a.z, tp[d0 + 2], w0);  w1 = fmaf(-b4.z, bp[d0 + 2], w1);
                w0 = fmaf(a.w, tp[d0 + 3], w0);  w1 = fmaf(-b4.w, bp[d0 + 3], w1);
            }
            sTmp[t] = w0 + w1;
        }
        __syncthreads();
        float cc = 0.f;
        if (t < 128) {
            g_wcomb[b][t] = (sTmp[t] + sTmp[t + 128]) + (sTmp[t + 256] + sTmp[t + 384]);
            cc = sbq[t] * sT[t];
        }
        #pragma unroll
        for (int off = 16; off > 0; off >>= 1)
            cc += __shfl_xor_sync(0xffffffffu, cc, off);
        if (lane == 0 && warp < 4) sred[warp] = cc;
        __syncthreads();
        if (t == 0) {
            g_ccomb[b] = sred[0] + sred[1] + sred[2] + sred[3];
            __threadfence();
            atomicExch(&g_flagW[b], 1);
        }
    }

    // ---------- load M into SMEM as tf32 ----------
    waitflag(&g_flagM, t);
    for (int idx = t; idx < Fn * Fn; idx += 512)
        sMu[(idx >> 7) * STM + (idx & 127)] = f2tf(__ldcg(&g_M[idx]));

    // ---------- Phase C: 4 tiles of 64 atoms; tf32 MMA + agg ----------
    float ccomb = 0.f;
    float n2local = 0.f;
    const int mb = (warp & 7) * 16;        // 8 row-groups
    const int ch = warp >> 3;              // col half 0/1
    for (int i = 0; i < 4; i++) {
        __syncthreads();   // prev-tile readers done; fences sMu stores (i=0)
        const float* aqb = aq + ((size_t)(b * Nn + atomBase + i * 64)) * Fn;
        #pragma unroll
        for (int it = 0; it < 4; it++) {
            int idx = 4 * t + 2048 * it;
            float4 v = *reinterpret_cast<const float4*>(aqb + idx);
            int f = idx & 127, a = idx >> 7;
            sXT[(f + 0) * STX + a] = v.x;
            sXT[(f + 1) * STX + a] = v.y;
            sXT[(f + 2) * STX + a] = v.z;
            sXT[(f + 3) * STX + a] = v.w;
            sXtfu[(f + 0) * STXF + a] = f2tf(v.x);
            sXtfu[(f + 1) * STXF + a] = f2tf(v.y);
            sXtfu[(f + 2) * STXF + a] = f2tf(v.z);
            sXtfu[(f + 3) * STXF + a] = f2tf(v.w);
        }
        __syncthreads();

        // Y[128 x 64] = M x X; warp owns 16 f-rows x 32 cols
        float yc[4][4];
        #pragma unroll
        for (int nb = 0; nb < 4; nb++)
            #pragma unroll
            for (int q = 0; q < 4; q++) yc[nb][q] = 0.f;

        #pragma unroll
        for (int kb = 0; kb < 16; kb++) {
            int k0 = kb * 8;
            unsigned a0 = sMu[(mb + gid) * STM + k0 + tid4];
            unsigned a1 = sMu[(mb + gid + 8) * STM + k0 + tid4];
            unsigned a2 = sMu[(mb + gid) * STM + k0 + tid4 + 4];
            unsigned a3 = sMu[(mb + gid + 8) * STM + k0 + tid4 + 4];
            #pragma unroll
            for (int nb = 0; nb < 4; nb++) {
                int col = ch * 32 + nb * 8 + gid;
                unsigned b0 = sXtfu[(k0 + tid4) * STXF + col];
                unsigned b1 = sXtfu[(k0 + tid4 + 4) * STXF + col];
                mma_tf32(yc[nb], a0, a1, a2, a3, b0, b1);
            }
        }
        #pragma unroll
        for (int nb = 0; nb < 4; nb++) {
            int col = ch * 32 + nb * 8 + 2 * tid4;
            *reinterpret_cast<float2*>(&sY[(mb + gid) * STY + col]) =
                make_float2(yc[nb][0], yc[nb][1]);
            *reinterpret_cast<float2*>(&sY[(mb + gid + 8) * STY + col]) =
                make_float2(yc[nb][2], yc[nb][3]);
        }

        if (i == 0) {   // fetch wcomb/ccomb (flag long set — A2 overlapped)
            waitflag(&g_flagW[b], t);
            if (t < 128) sWc[t] = __ldcg(&g_wcomb[b][t]);
            __syncthreads();
            ccomb = __ldcg(&g_ccomb[b]);
        }
        __syncthreads();   // sY ready

        float wc[4];
        #pragma unroll
        for (int k = 0; k < 4; k++) wc[k] = sWc[lane + 32 * k];

        const int r0 = warp * 4;           // 16 warps x 4 atoms
        #pragma unroll
        for (int a = 0; a < 4; a++) {
            float p1 = 0.f, p2 = 0.f;
            #pragma unroll
            for (int k = 0; k < 4; k++) {
                int f = lane + 32 * k;
                float xf = sXT[f * STX + r0 + a];
                float yf = sY[f * STY + r0 + a];
                p1 = fmaf(xf, yf, p1);
                p2 = fmaf(xf, wc[k], p2);
            }
            #pragma unroll
            for (int off = 16; off > 0; off >>= 1) {
                p1 += __shfl_xor_sync(0xffffffffu, p1, off);
                p2 += __shfl_xor_sync(0xffffffffu, p2, off);
            }
            if (lane == 0) {
                float mv = sMaskAll[i * 64 + r0 + a];
                float aggv = mv * DKC * (p2 + ccomb - p1);
                aggAll[i * 64 + r0 + a] = aggv;
                n2local = fmaf(aggv, aggv, n2local);
            }
        }
    }
    if (lane == 0) sred[warp] = n2local;
    __syncthreads();
    if (t == 0) {
        float s = 0.f;
        #pragma unroll
        for (int w = 0; w < 16; w++) s += sred[w];
        g_n2part[b][j] = s;
        __threadfence();
        if (atomicAdd(&g_cnt2[b], 1) == 3) {
            float n2 = 0.f;
            #pragma unroll
            for (int c = 0; c < 4; c++) n2 += __ldcg(&g_n2part[b][c]);
            g_invn[b] = rsqrtf(n2);
            __threadfence();
            atomicExch(&g_flagN[b], 1);
        }
    }

    // ---------- Phase D: exp, Z partial, weighted colsum (direct gmem, L2-hot) ----------
    waitflag(&g_flagN[b], t);
    const float invn = __ldcg(&g_invn[b]);
    float e = 0.f;
    if (t < 256) e = (sMaskAll[t] != 0.f) ? __expf(aggAll[t] * invn) : 0.f;
    __syncthreads();
    if (t < 256) aggAll[t] = e;            // now holds e values
    float ze = e;
    #pragma unroll
    for (int off = 16; off > 0; off >>= 1) ze += __shfl_xor_sync(0xffffffffu, ze, off);
    if (lane == 0 && warp < 8) sred[warp] = ze;
    __syncthreads();

    {   // u'[f] = sum_r e_r * aq[r][f], direct from gmem (L2-hot), float4
        int fq = (t & 31) * 4, rg = t >> 5;    // 16 groups x 16 rows
        const float* pp = aq + ((size_t)(b * Nn + atomBase + rg * 16)) * Fn + fq;
        const float* ep = &aggAll[rg * 16];
        float4 s0 = {0,0,0,0}, s1 = {0,0,0,0};
        #pragma unroll
        for (int r = 0; r < 16; r += 2) {
            float w0 = ep[r], w1 = ep[r + 1];
            float4 v0 = *reinterpret_cast<const float4*>(pp + (r + 0) * Fn);
            float4 v1 = *reinterpret_cast<const float4*>(pp + (r + 1) * Fn);
            s0.x = fmaf(w0, v0.x, s0.x); s0.y = fmaf(w0, v0.y, s0.y);
            s0.z = fmaf(w0, v0.z, s0.z); s0.w = fmaf(w0, v0.w, s0.w);
            s1.x = fmaf(w1, v1.x, s1.x); s1.y = fmaf(w1, v1.y, s1.y);
            s1.z = fmaf(w1, v1.z, s1.z); s1.w = fmaf(w1, v1.w, s1.w);
        }
        sStage[rg * 128 + fq + 0] = s0.x + s1.x;
        sStage[rg * 128 + fq + 1] = s0.y + s1.y;
        sStage[rg * 128 + fq + 2] = s0.z + s1.z;
        sStage[rg * 128 + fq + 3] = s0.w + s1.w;
    }
    __syncthreads();
    if (t < 128) {
        float s = 0.f;
        #pragma unroll
        for (int g = 0; g < 16; g++) s += sStage[g * 128 + t];
        g_upart[b][j][t] = s;
    }
    if (t == 0) {
        float z = 0.f;
        #pragma unroll
        for (int w = 0; w < 8; w++) z += sred[w];
        g_Zpart[b][j] = z;
    }
    __threadfence();
    __syncthreads();
    if (t == 0) {
        isL3 = (atomicAdd(&g_cnt3[b], 1) == 3);
        if (isL3) {
            float Z = 0.f;
            #pragma unroll
            for (int c = 0; c < 4; c++) Z += __ldcg(&g_Zpart[b][c]);
            g_invZ[b] = 1.0f / Z;
            __threadfence();
            atomicExch(&g_flagZ[b], 1);
        }
    }
    __syncthreads();

    // ---------- Phase E: attn out; last block computes context ----------
    waitflag(&g_flagZ[b], t);
    const float invZ = __ldcg(&g_invZ[b]);
    if (attn_out && t < 256) attn_out[b * Nn + atomBase + t] = aggAll[t] * invZ;
    __syncthreads();

    if (isL3) {
        float* sU = sTmp;       // [0..127] reduced u vector
        float* spart = sm;      // extern SMEM region is dead here
        if (t < 128) {
            float s = 0.f;
            #pragma unroll
            for (int c = 0; c < 4; c++) s += __ldcg(&g_upart[b][c][t]);
            sU[t] = s;
        }
        __syncthreads();
        if (ctx_out && t < 256) {
            int g = t >> 7, d = t & 127;
            int f0 = g * 64;
            float c0 = 0.f, c1 = 0.f, c2 = 0.f, c3 = 0.f;
            #pragma unroll 4
            for (int f = f0; f < f0 + 64; f += 4) {
                c0 = fmaf(Wv[(f + 0) * Fn + d], sU[f + 0], c0);
                c1 = fmaf(Wv[(f + 1) * Fn + d], sU[f + 1], c1);
                c2 = fmaf(Wv[(f + 2) * Fn + d], sU[f + 2], c2);
                c3 = fmaf(Wv[(f + 3) * Fn + d], sU[f + 3], c3);
            }
            spart[t] = (c0 + c1) + (c2 + c3);
        }
        __syncthreads();
        if (ctx_out && t < 128)
            ctx_out[b * Dn + t] = (spart[t] + spart[t + 128]) * invZ + bv[t];
    }

    // ---------- reset for graph replay ----------
    __threadfence();
    __syncthreads();
    if (t == 0) {
        if (atomicAdd(&g_cnt4[b], 1) == 3) {
            g_cnt1[b] = 0; g_cnt2[b] = 0; g_cnt3[b] = 0; g_cnt4[b] = 0;
            g_flagW[b] = 0; g_flagN[b] = 0; g_flagZ[b] = 0;
            if (atomicAdd(&g_cntR, 1) == 31) {
                g_cntM = 0; g_flagM = 0; g_cntR = 0;
            }
        }
    }
}

// ---------------- host launch ----------------
extern "C" void kernel_launch(void* const* d_in, const int* in_sizes, int n_in,
                              void* d_out, int out_size) {
    const float* aq   = (const float*)d_in[0];
    const float* mask = (const float*)d_in[1];
    const float* Wq   = (const float*)d_in[2];
    const float* bq   = (const float*)d_in[3];
    const float* Wk   = (const float*)d_in[4];
    const float* bk   = (const float*)d_in[5];
    const float* Wv   = (const float*)d_in[6];
    const float* bv   = (const float*)d_in[7];

    float* out = (float*)d_out;
    float* attn_out = nullptr;
    float* ctx_out = nullptr;
    if (out_size >= Bn * Nn + Bn * Dn) { attn_out = out; ctx_out = out + Bn * Nn; }
    else if (out_size == Bn * Nn)      { attn_out = out; }
    else                               { ctx_out = out; }

    cudaFuncSetAttribute(k1, cudaFuncAttributeMaxDynamicSharedMemorySize, K1_SMEM);

    k1<<<128, 512, K1_SMEM>>>(aq, mask, Wq, Wk, bq, bk, Wv, bv,
                              attn_out, ctx_out);
}

// round 11
// speedup vs baseline: 1.7324x; 1.7324x over previous
#include <cuda_runtime.h>
#include <math.h>

#define Bn 32
#define Nn 1024
#define Fn 128
#define Dn 128

// dk = (D^-0.5)/N = 1/(sqrt(128)*1024)
#define DKC 8.6316745750311e-05f

// ---------------- scratch (device globals) ----------------
__device__ float g_M[Fn * Fn];
__device__ float g_Apart[Bn][4][Fn];
__device__ float g_wcomb[Bn][Fn];
__device__ float g_ccomb[Bn];
__device__ float g_n2part[Bn][4];
__device__ float g_invn[Bn];
__device__ float g_Zpart[Bn][4];
__device__ float g_upart[Bn][4][Fn];
__device__ float g_invZ[Bn];
__device__ int   g_cnt1[Bn], g_cnt2[Bn], g_cnt3[Bn], g_cnt4[Bn];
__device__ int   g_flagW[Bn], g_flagN[Bn], g_flagZ[Bn];
__device__ int   g_cntM, g_flagM, g_cntR;

// ---------------- helpers ----------------
__device__ __forceinline__ void mma_tf32(float c[4], unsigned a0, unsigned a1,
                                         unsigned a2, unsigned a3,
                                         unsigned b0, unsigned b1) {
    asm("mma.sync.aligned.m16n8k8.row.col.f32.tf32.tf32.f32 "
        "{%0,%1,%2,%3}, {%4,%5,%6,%7}, {%8,%9}, {%0,%1,%2,%3};"
        : "+f"(c[0]), "+f"(c[1]), "+f"(c[2]), "+f"(c[3])
        : "r"(a0), "r"(a1), "r"(a2), "r"(a3), "r"(b0), "r"(b1));
}
__device__ __forceinline__ void waitflag(int* f, int t) {
    if (t == 0) { while (atomicAdd(f, 0) == 0) __nanosleep(64); }
    __syncthreads();
    __threadfence();
}

// ============ k1: persistent fused kernel, 128 blocks x 256 threads ============
#define STM 132      // M row stride (u32 words) — conflict-free A-frags
#define STA 132      // atom-major X/Y stride — conflict-free everywhere
#define K1_SMEM ((Fn * STM + 64 * STA + 64 * STA) * 4)

__global__ void __launch_bounds__(256, 1) k1(const float* __restrict__ aq,
                                             const float* __restrict__ mask,
                                             const float* __restrict__ Wq,
                                             const float* __restrict__ Wk,
                                             const float* __restrict__ bq,
                                             const float* __restrict__ bk,
                                             const float* __restrict__ Wv,
                                             const float* __restrict__ bv,
                                             float* __restrict__ attn_out,
                                             float* __restrict__ ctx_out) {
    extern __shared__ float sm[];
    float*    sMf = sm;                      // [128][132] M (raw f32, fed as tf32)
    unsigned* sMu = (unsigned*)sm;
    float*    sX  = sm + Fn * STM;           // [64 atom][132] fp32 tile (atom-major)
    unsigned* sXu = (unsigned*)sX;
    float*    sY  = sX + 64 * STA;           // [64 atom][132] Y
    __shared__ float sWq[128], sA[128], sT[128], sbq[128], sWc[128];
    __shared__ float sMaskAll[256], aggAll[256];
    __shared__ float sStage[1024], sTmp[256], sred[8];
    __shared__ int isL1, isL3;

    const int p = blockIdx.x;            // 0..127
    const int b = p >> 2, j = p & 3;     // batch, quarter
    const int t = threadIdx.x;
    const int warp = t >> 5, lane = t & 31;
    const int gid = lane >> 2, tid4 = lane & 3;
    const int atomBase = j * 256;
    const int mb = warp * 16;

    // ---------- A0: compute M row p ----------
    if (t < 128) sWq[t] = Wq[p * Fn + t];
    __syncthreads();
    {
        int c = t & 127, hh = (t >> 7) * 64;
        const float4* wk4 = reinterpret_cast<const float4*>(Wk + c * Fn + hh);
        const float* sq = sWq + hh;
        float a0 = 0.f, a1 = 0.f, a2 = 0.f, a3 = 0.f;
        #pragma unroll
        for (int q = 0; q < 16; q += 4) {
            float4 v0 = wk4[q], v1 = wk4[q + 1], v2 = wk4[q + 2], v3 = wk4[q + 3];
            a0 = fmaf(sq[4*q + 0], v0.x, a0); a0 = fmaf(sq[4*q + 1], v0.y, a0);
            a0 = fmaf(sq[4*q + 2], v0.z, a0); a0 = fmaf(sq[4*q + 3], v0.w, a0);
            a1 = fmaf(sq[4*q + 4], v1.x, a1); a1 = fmaf(sq[4*q + 5], v1.y, a1);
            a1 = fmaf(sq[4*q + 6], v1.z, a1); a1 = fmaf(sq[4*q + 7], v1.w, a1);
            a2 = fmaf(sq[4*q + 8], v2.x, a2); a2 = fmaf(sq[4*q + 9], v2.y, a2);
            a2 = fmaf(sq[4*q +10], v2.z, a2); a2 = fmaf(sq[4*q +11], v2.w, a2);
            a3 = fmaf(sq[4*q +12], v3.x, a3); a3 = fmaf(sq[4*q +13], v3.y, a3);
            a3 = fmaf(sq[4*q +14], v3.z, a3); a3 = fmaf(sq[4*q +15], v3.w, a3);
        }
        sTmp[t] = (a0 + a1) + (a2 + a3);
    }
    __syncthreads();
    if (t < 128) g_M[p * Fn + t] = sTmp[t] + sTmp[t + 128];
    __threadfence();
    __syncthreads();
    if (t == 0 && atomicAdd(&g_cntM, 1) == 127) atomicExch(&g_flagM, 1);

    // ---------- A1: colsum of my 256 atoms (cold gmem, coalesced float4) ----------
    {
        int fq = (t & 31) * 4, rg = t >> 5;      // 8 groups x 32 rows
        const float* pp = aq + ((size_t)(b * Nn + atomBase + rg * 32)) * Fn + fq;
        float4 s0 = {0,0,0,0}, s1 = {0,0,0,0}, s2 = {0,0,0,0}, s3 = {0,0,0,0};
        #pragma unroll
        for (int r = 0; r < 32; r += 4) {
            float4 v0 = *reinterpret_cast<const float4*>(pp + (r + 0) * Fn);
            float4 v1 = *reinterpret_cast<const float4*>(pp + (r + 1) * Fn);
            float4 v2 = *reinterpret_cast<const float4*>(pp + (r + 2) * Fn);
            float4 v3 = *reinterpret_cast<const float4*>(pp + (r + 3) * Fn);
            s0.x += v0.x; s0.y += v0.y; s0.z += v0.z; s0.w += v0.w;
            s1.x += v1.x; s1.y += v1.y; s1.z += v1.z; s1.w += v1.w;
            s2.x += v2.x; s2.y += v2.y; s2.z += v2.z; s2.w += v2.w;
            s3.x += v3.x; s3.y += v3.y; s3.z += v3.z; s3.w += v3.w;
        }
        sStage[rg * 128 + fq + 0] = (s0.x + s1.x) + (s2.x + s3.x);
        sStage[rg * 128 + fq + 1] = (s0.y + s1.y) + (s2.y + s3.y);
        sStage[rg * 128 + fq + 2] = (s0.z + s1.z) + (s2.z + s3.z);
        sStage[rg * 128 + fq + 3] = (s0.w + s1.w) + (s2.w + s3.w);
    }
    sMaskAll[t] = mask[b * Nn + atomBase + t];
    __syncthreads();
    if (t < 128) {
        float s = 0.f;
        #pragma unroll
        for (int g = 0; g < 8; g++) s += sStage[g * 128 + t];
        g_Apart[b][j][t] = s;
    }
    __threadfence();
    __syncthreads();
    if (t == 0) isL1 = (atomicAdd(&g_cnt1[b], 1) == 3);
    __syncthreads();

    // ---------- A2: last block of batch computes wcomb/ccomb ----------
    if (isL1) {
        if (t < 128) {
            float s = 0.f;
            #pragma unroll
            for (int c = 0; c < 4; c++) s += __ldcg(&g_Apart[b][c][t]);
            sA[t] = s;
            sbq[t] = bq[t];
        }
        __syncthreads();
        if (t < 128) {
            float s0 = 0.f, s1 = 0.f, s2 = 0.f, s3 = 0.f;
            #pragma unroll 8
            for (int f = 0; f < Fn; f += 4) {
                s0 = fmaf(Wk[(f + 0) * Fn + t], sA[f + 0], s0);
                s1 = fmaf(Wk[(f + 1) * Fn + t], sA[f + 1], s1);
                s2 = fmaf(Wk[(f + 2) * Fn + t], sA[f + 2], s2);
                s3 = fmaf(Wk[(f + 3) * Fn + t], sA[f + 3], s3);
            }
            sT[t] = (s0 + s1) + (s2 + s3) + 1023.0f * bk[t];  // S - bk
        }
        __syncthreads();
        float cc = 0.f;
        if (t < 128) {
            const float4* wq4 = reinterpret_cast<const float4*>(Wq + t * Fn);
            const float4* wk4 = reinterpret_cast<const float4*>(Wk + t * Fn);
            float w0 = 0.f, w1 = 0.f, w2 = 0.f, w3 = 0.f;
            #pragma unroll 8
            for (int q = 0; q < 32; q += 2) {
                float4 a = wq4[q], b4 = wk4[q], c4 = wq4[q + 1], d4 = wk4[q + 1];
                int d0 = 4 * q, d1 = 4 * q + 4;
                w0 = fmaf(a.x, sT[d0 + 0], w0);  w1 = fmaf(-b4.x, sbq[d0 + 0], w1);
                w0 = fmaf(a.y, sT[d0 + 1], w0);  w1 = fmaf(-b4.y, sbq[d0 + 1], w1);
                w0 = fmaf(a.z, sT[d0 + 2], w0);  w1 = fmaf(-b4.z, sbq[d0 + 2], w1);
                w0 = fmaf(a.w, sT[d0 + 3], w0);  w1 = fmaf(-b4.w, sbq[d0 + 3], w1);
                w2 = fmaf(c4.x, sT[d1 + 0], w2); w3 = fmaf(-d4.x, sbq[d1 + 0], w3);
                w2 = fmaf(c4.y, sT[d1 + 1], w2); w3 = fmaf(-d4.y, sbq[d1 + 1], w3);
                w2 = fmaf(c4.z, sT[d1 + 2], w2); w3 = fmaf(-d4.z, sbq[d1 + 2], w3);
                w2 = fmaf(c4.w, sT[d1 + 3], w2); w3 = fmaf(-d4.w, sbq[d1 + 3], w3);
            }
            g_wcomb[b][t] = (w0 + w1) + (w2 + w3);
            cc = sbq[t] * sT[t];
        }
        #pragma unroll
        for (int off = 16; off > 0; off >>= 1)
            cc += __shfl_xor_sync(0xffffffffu, cc, off);
        if (lane == 0 && warp < 4) sred[warp] = cc;
        __syncthreads();
        if (t == 0) {
            g_ccomb[b] = sred[0] + sred[1] + sred[2] + sred[3];
            __threadfence();
            atomicExch(&g_flagW[b], 1);
        }
    }

    // ---------- load M into SMEM (raw f32 bits; truncated to tf32 by MMA) ----------
    waitflag(&g_flagM, t);
    #pragma unroll
    for (int it = 0; it < 8; it++) {
        int idx4 = t + 256 * it;                 // float4 index over 128x128
        int f = idx4 >> 5, c4 = (idx4 & 31) * 4;
        *reinterpret_cast<float4*>(&sMf[f * STM + c4]) =
            *reinterpret_cast<const float4*>(&g_M[f * Fn + c4]);
    }

    // ---------- Phase C: 4 tiles of 64 atoms; tf32 MMA + agg (prefetched) ----------
    float ccomb = 0.f;
    float n2local = 0.f;
    float4 pf[8];
    {
        const float* aqb = aq + ((size_t)(b * Nn + atomBase)) * Fn;
        #pragma unroll
        for (int it = 0; it < 8; it++)
            pf[it] = *reinterpret_cast<const float4*>(aqb + 4 * (t + 256 * it));
    }
    for (int i = 0; i < 4; i++) {
        __syncthreads();   // prev-tile readers done; fences sMf stores (i=0)
        #pragma unroll
        for (int it = 0; it < 8; it++) {
            int idx4 = t + 256 * it;             // [atom][f] row-major tile
            int atom = idx4 >> 5, f4 = (idx4 & 31) * 4;
            *reinterpret_cast<float4*>(&sX[atom * STA + f4]) = pf[it];
        }
        __syncthreads();
        if (i < 3) {       // prefetch next tile; latency hides under MMA
            const float* aqb = aq + ((size_t)(b * Nn + atomBase + (i + 1) * 64)) * Fn;
            #pragma unroll
            for (int it = 0; it < 8; it++)
                pf[it] = *reinterpret_cast<const float4*>(aqb + 4 * (t + 256 * it));
        }

        // Y[64 atoms x 128 f] = (M X)^T; warp owns f-rows mb..mb+15, all 64 atoms
        float yc[8][4];
        #pragma unroll
        for (int nb = 0; nb < 8; nb++)
            #pragma unroll
            for (int q = 0; q < 4; q++) yc[nb][q] = 0.f;

        #pragma unroll
        for (int kb = 0; kb < 16; kb++) {
            int k0 = kb * 8;
            unsigned a0 = sMu[(mb + gid) * STM + k0 + tid4];
            unsigned a1 = sMu[(mb + gid + 8) * STM + k0 + tid4];
            unsigned a2 = sMu[(mb + gid) * STM + k0 + tid4 + 4];
            unsigned a3 = sMu[(mb + gid + 8) * STM + k0 + tid4 + 4];
            #pragma unroll
            for (int nb = 0; nb < 8; nb++) {
                int col = nb * 8 + gid;          // atom index
                unsigned b0 = sXu[col * STA + k0 + tid4];
                unsigned b1 = sXu[col * STA + k0 + tid4 + 4];
                mma_tf32(yc[nb], a0, a1, a2, a3, b0, b1);
            }
        }
        #pragma unroll
        for (int nb = 0; nb < 8; nb++) {
            int col = nb * 8 + 2 * tid4;         // atom index
            sY[(col    ) * STA + mb + gid    ] = yc[nb][0];
            sY[(col + 1) * STA + mb + gid    ] = yc[nb][1];
            sY[(col    ) * STA + mb + gid + 8] = yc[nb][2];
            sY[(col + 1) * STA + mb + gid + 8] = yc[nb][3];
        }

        if (i == 0) {   // fetch wcomb/ccomb (flag long set — A2 overlapped)
            waitflag(&g_flagW[b], t);
            if (t < 128) sWc[t] = __ldcg(&g_wcomb[b][t]);
            __syncthreads();
            ccomb = __ldcg(&g_ccomb[b]);
        }
        __syncthreads();   // sY ready

        const float4 wcv = *reinterpret_cast<const float4*>(&sWc[4 * lane]);
        #pragma unroll
        for (int a = 0; a < 8; a++) {
            int atom = warp * 8 + a;
            float4 xv = *reinterpret_cast<const float4*>(&sX[atom * STA + 4 * lane]);
            float4 yv = *reinterpret_cast<const float4*>(&sY[atom * STA + 4 * lane]);
            float p1 = xv.x * yv.x;
            p1 = fmaf(xv.y, yv.y, p1);
            p1 = fmaf(xv.z, yv.z, p1);
            p1 = fmaf(xv.w, yv.w, p1);
            float p2 = xv.x * wcv.x;
            p2 = fmaf(xv.y, wcv.y, p2);
            p2 = fmaf(xv.z, wcv.z, p2);
            p2 = fmaf(xv.w, wcv.w, p2);
            #pragma unroll
            for (int off = 16; off > 0; off >>= 1) {
                p1 += __shfl_xor_sync(0xffffffffu, p1, off);
                p2 += __shfl_xor_sync(0xffffffffu, p2, off);
            }
            if (lane == 0) {
                float mv = sMaskAll[i * 64 + atom];
                float aggv = mv * DKC * (p2 + ccomb - p1);
                aggAll[i * 64 + atom] = aggv;
                n2local = fmaf(aggv, aggv, n2local);
            }
        }
    }
    if (lane == 0) sred[warp] = n2local;
    __syncthreads();
    if (t == 0) {
        float s = 0.f;
        #pragma unroll
        for (int w = 0; w < 8; w++) s += sred[w];
        g_n2part[b][j] = s;
        __threadfence();
        if (atomicAdd(&g_cnt2[b], 1) == 3) {
            float n2 = 0.f;
            #pragma unroll
            for (int c = 0; c < 4; c++) n2 += __ldcg(&g_n2part[b][c]);
            g_invn[b] = rsqrtf(n2);
            __threadfence();
            atomicExch(&g_flagN[b], 1);
        }
    }

    // ---------- Phase D: exp, Z partial, weighted colsum (direct gmem, L2-hot) ----------
    waitflag(&g_flagN[b], t);
    const float invn = __ldcg(&g_invn[b]);
    float e = (sMaskAll[t] != 0.f) ? __expf(aggAll[t] * invn) : 0.f;
    __syncthreads();
    aggAll[t] = e;          // now holds e values
    float ze = e;
    #pragma unroll
    for (int off = 16; off > 0; off >>= 1) ze += __shfl_xor_sync(0xffffffffu, ze, off);
    if (lane == 0) sred[warp] = ze;
    __syncthreads();        // aggAll (e) published

    {   // u'[f] = sum_r e_r * aq[r][f], direct from gmem (L2-hot), float4
        int fq = (t & 31) * 4, rg = t >> 5;    // 8 groups x 32 rows
        const float* pp = aq + ((size_t)(b * Nn + atomBase + rg * 32)) * Fn + fq;
        const float* ep = &aggAll[rg * 32];
        float4 s0 = {0,0,0,0}, s1 = {0,0,0,0};
        #pragma unroll
        for (int r = 0; r < 32; r += 2) {
            float w0 = ep[r], w1 = ep[r + 1];
            float4 v0 = *reinterpret_cast<const float4*>(pp + (r + 0) * Fn);
            float4 v1 = *reinterpret_cast<const float4*>(pp + (r + 1) * Fn);
            s0.x = fmaf(w0, v0.x, s0.x); s0.y = fmaf(w0, v0.y, s0.y);
            s0.z = fmaf(w0, v0.z, s0.z); s0.w = fmaf(w0, v0.w, s0.w);
            s1.x = fmaf(w1, v1.x, s1.x); s1.y = fmaf(w1, v1.y, s1.y);
            s1.z = fmaf(w1, v1.z, s1.z); s1.w = fmaf(w1, v1.w, s1.w);
        }
        sStage[rg * 128 + fq + 0] = s0.x + s1.x;
        sStage[rg * 128 + fq + 1] = s0.y + s1.y;
        sStage[rg * 128 + fq + 2] = s0.z + s1.z;
        sStage[rg * 128 + fq + 3] = s0.w + s1.w;
    }
    __syncthreads();
    if (t < 128) {
        float s = 0.f;
        #pragma unroll
        for (int g = 0; g < 8; g++) s += sStage[g * 128 + t];
        g_upart[b][j][t] = s;
    }
    if (t == 0) {
        float z = 0.f;
        #pragma unroll
        for (int w = 0; w < 8; w++) z += sred[w];
        g_Zpart[b][j] = z;
    }
    __threadfence();
    __syncthreads();
    if (t == 0) {
        isL3 = (atomicAdd(&g_cnt3[b], 1) == 3);
        if (isL3) {
            float Z = 0.f;
            #pragma unroll
            for (int c = 0; c < 4; c++) Z += __ldcg(&g_Zpart[b][c]);
            g_invZ[b] = 1.0f / Z;
            __threadfence();
            atomicExch(&g_flagZ[b], 1);
        }
    }
    __syncthreads();

    // ---------- Phase E: attn out; last block computes context ----------
    waitflag(&g_flagZ[b], t);
    const float invZ = __ldcg(&g_invZ[b]);
    if (attn_out) attn_out[b * Nn + atomBase + t] = aggAll[t] * invZ;
    __syncthreads();

    if (isL3) {
        float* sU = sTmp;       // [0..127] reduced u vector
        float* spart = sm;      // extern SMEM region is dead here
        if (t < 128) {
            float s = 0.f;
            #pragma unroll
            for (int c = 0; c < 4; c++) s += __ldcg(&g_upart[b][c][t]);
            sU[t] = s;
        }
        __syncthreads();
        if (ctx_out) {
            int g = t >> 7, d = t & 127;
            int f0 = g * 64;
            float c0 = 0.f, c1 = 0.f, c2 = 0.f, c3 = 0.f;
            #pragma unroll 4
            for (int f = f0; f < f0 + 64; f += 4) {
                c0 = fmaf(Wv[(f + 0) * Fn + d], sU[f + 0], c0);
                c1 = fmaf(Wv[(f + 1) * Fn + d], sU[f + 1], c1);
                c2 = fmaf(Wv[(f + 2) * Fn + d], sU[f + 2], c2);
                c3 = fmaf(Wv[(f + 3) * Fn + d], sU[f + 3], c3);
            }
            spart[t] = (c0 + c1) + (c2 + c3);
            __syncthreads();
            if (t < 128)
                ctx_out[b * Dn + t] = (spart[t] + spart[t + 128]) * invZ + bv[t];
        }
    }

    // ---------- reset for graph replay ----------
    __threadfence();
    __syncthreads();
    if (t == 0) {
        if (atomicAdd(&g_cnt4[b], 1) == 3) {
            g_cnt1[b] = 0; g_cnt2[b] = 0; g_cnt3[b] = 0; g_cnt4[b] = 0;
            g_flagW[b] = 0; g_flagN[b] = 0; g_flagZ[b] = 0;
            if (atomicAdd(&g_cntR, 1) == 31) {
                g_cntM = 0; g_flagM = 0; g_cntR = 0;
            }
        }
    }
}

// ---------------- host launch ----------------
extern "C" void kernel_launch(void* const* d_in, const int* in_sizes, int n_in,
                              void* d_out, int out_size) {
    const float* aq   = (const float*)d_in[0];
    const float* mask = (const float*)d_in[1];
    const float* Wq   = (const float*)d_in[2];
    const float* bq   = (const float*)d_in[3];
    const float* Wk   = (const float*)d_in[4];
    const float* bk   = (const float*)d_in[5];
    const float* Wv   = (const float*)d_in[6];
    const float* bv   = (const float*)d_in[7];

    float* out = (float*)d_out;
    float* attn_out = nullptr;
    float* ctx_out = nullptr;
    if (out_size >= Bn * Nn + Bn * Dn) { attn_out = out; ctx_out = out + Bn * Nn; }
    else if (out_size == Bn * Nn)      { attn_out = out; }
    else                               { ctx_out = out; }

    cudaFuncSetAttribute(k1, cudaFuncAttributeMaxDynamicSharedMemorySize, K1_SMEM);

    k1<<<128, 256, K1_SMEM>>>(aq, mask, Wq, Wk, bq, bk, Wv, bv,
                              attn_out, ctx_out);
}